// round 2
// baseline (speedup 1.0000x reference)
#include <cuda_runtime.h>
#include <cstdint>

#define NBOX 8192
#define M 64
#define D_IN 2376
#define H 1024
#define NCLS 150
#define IOU_T 0.01f

typedef unsigned int u32;
typedef unsigned short u16;
typedef unsigned char u8;

// -------- persistent device scratch (allocation-free rule) --------
__device__ int   g_sel[M];
__device__ float g_emb[M * 200];
__device__ float g_pos[M * 128];
__device__ float g_h1[M * H];
__device__ float g_h2[M * H];
__device__ float g_part[1048576];     // split-K partials: [slice*CB+cb][64*64]
__device__ int   g_cnt[16];           // arrival counters per column tile

// ============================================================
// smem layout for sortnms kernel (bytes)
// ============================================================
#define RS_KEYA 0         // u32[8192]  32KB
#define RS_KEYB 32768     // u32[8192]  32KB
#define RS_IDXA 65536     // u16[8192]  16KB
#define RS_IDXB 81920     // u16[8192]  16KB
#define RS_GH   98304     // u32[256][16] 16KB
#define RS_RNK  114688    // u8[8192]   8KB
#define RS_TOT  122880    // u32[16]
#define RS_BASE 122944    // u32[16]
#define RS_SEL  123008    // int[64]
#define RS_SUPP 123264    // int[64]
#define RS_ST   123520    // int[4]
#define RS_CB   32768     // alias keyB: float4[1024] NMS candidate boxes
#define RS_CORD 81920     // alias idxB: int[1024] NMS candidate orig idx
#define SORT_SMEM 123584

__device__ __forceinline__ bool iou_gt(float4 k, float ka, float4 c, float ca) {
    float ix1 = fmaxf(k.x, c.x), iy1 = fmaxf(k.y, c.y);
    float ix2 = fminf(k.z, c.z), iy2 = fminf(k.w, c.w);
    float iw = fmaxf(ix2 - ix1, 0.f), ih = fmaxf(iy2 - iy1, 0.f);
    float inter = iw * ih;
    return inter > IOU_T * (ka + ca - inter + 1e-9f);
}

// ============================================================
// Kernel 1: radix sort + greedy NMS + select + pos/embed prep
// Single block, 1024 threads.
// ============================================================
__global__ void __launch_bounds__(1024) sortnms_kernel(
    const float* __restrict__ scores, const float* __restrict__ boxes,
    const int* __restrict__ labels, const float* __restrict__ embed_w,
    const float* __restrict__ bn_pos, const float* __restrict__ pos_w,
    const float* __restrict__ pos_b,
    float* __restrict__ d_out, int out_size)
{
    extern __shared__ unsigned char sm[];
    u32* keyA = (u32*)(sm + RS_KEYA);
    u32* keyB = (u32*)(sm + RS_KEYB);
    u16* idxA = (u16*)(sm + RS_IDXA);
    u16* idxB = (u16*)(sm + RS_IDXB);
    u32* gh   = (u32*)(sm + RS_GH);
    u8*  rnk  = (u8*) (sm + RS_RNK);
    u32* tot  = (u32*)(sm + RS_TOT);
    u32* base = (u32*)(sm + RS_BASE);
    int* s_sel  = (int*)(sm + RS_SEL);
    int* s_supp = (int*)(sm + RS_SUPP);
    int* st     = (int*)(sm + RS_ST);
    float4* cbx = (float4*)(sm + RS_CB);
    int*    cord = (int*)(sm + RS_CORD);

    const int tid = threadIdx.x;
    const int lane = tid & 31;
    const int wrp = tid >> 5;
    const float4* boxes4 = (const float4*)boxes;

    // ---- build sortable keys: ascending sort on ~f(bits) == descending score,
    //      stable ties -> ascending original index (matches argsort(-scores)) ----
    for (int t = tid; t < NBOX; t += 1024) {
        u32 b = __float_as_uint(scores[t]);
        u32 f = b ^ ((b >> 31) ? 0xFFFFFFFFu : 0x80000000u);
        keyA[t] = ~f;
        idxA[t] = (u16)t;
    }
    __syncthreads();

    // ---- 8-pass stable LSD radix sort (4-bit digits) ----
    u32 *src = keyA, *dst = keyB;
    u16 *isrc = idxA, *idst = idxB;
    for (int p = 0; p < 8; ++p) {
        const int sh = p * 4;
        for (int t = tid; t < 4096; t += 1024) gh[t] = 0;
        __syncthreads();
        // phase A: per-group (32 elems) histogram + within-group rank
        #pragma unroll
        for (int it = 0; it < 8; ++it) {
            int g = it * 32 + wrp;
            int e = g * 32 + lane;
            u32 k = src[e];
            int d = (k >> sh) & 15;
            unsigned m = __match_any_sync(0xffffffffu, d);
            unsigned lt = m & ((1u << lane) - 1u);
            rnk[e] = (u8)__popc(lt);
            if (lt == 0) gh[g * 16 + d] = __popc(m);
        }
        __syncthreads();
        // phase B: per-digit exclusive scan over 256 groups (warps 0..15)
        if (wrp < 16) {
            const int d = wrp;
            u32 carry = 0;
            #pragma unroll
            for (int it = 0; it < 8; ++it) {
                int g = it * 32 + lane;
                u32 v = gh[g * 16 + d];
                u32 x = v;
                #pragma unroll
                for (int o = 1; o < 32; o <<= 1) {
                    u32 y = __shfl_up_sync(0xffffffffu, x, o);
                    if (lane >= o) x += y;
                }
                gh[g * 16 + d] = x - v + carry;
                carry += __shfl_sync(0xffffffffu, x, 31);
            }
            if (lane == 0) tot[d] = carry;
        }
        __syncthreads();
        if (wrp == 0 && lane < 16) {
            u32 v = tot[lane];
            u32 x = v;
            #pragma unroll
            for (int o = 1; o < 16; o <<= 1) {
                u32 y = __shfl_up_sync(0xffffu, x, o);
                if (lane >= o) x += y;
            }
            base[lane] = x - v;
        }
        __syncthreads();
        // phase C: stable scatter
        #pragma unroll
        for (int it = 0; it < 8; ++it) {
            int g = it * 32 + wrp;
            int e = g * 32 + lane;
            u32 k = src[e];
            int d = (k >> sh) & 15;
            u32 pos = base[d] + gh[g * 16 + d] + rnk[e];
            dst[pos] = k;
            idst[pos] = isrc[e];
        }
        __syncthreads();
        u32* tk = src; src = dst; dst = tk;
        u16* ti = isrc; isrc = idst; idst = ti;
    }
    // after 8 passes: sorted order lives in keyA/idxA (src/isrc == A buffers)

    // ---- greedy NMS, warp 0 sequential, chunked candidate staging ----
    float4 kb0 = make_float4(0, 0, 0, 0), kb1 = make_float4(0, 0, 0, 0);
    float ka0 = 0.f, ka1 = 0.f;
    int kept = 0, supp = 0;
    if (tid == 0) { st[0] = 0; st[1] = 0; }

    for (int c0 = 0; c0 < NBOX; c0 += 1024) {
        __syncthreads();
        {
            int oi = (int)isrc[c0 + tid];
            cord[tid] = oi;
            cbx[tid] = boxes4[oi];
        }
        __syncthreads();

        if (tid < 32) {
            #pragma unroll 1
            for (int ii = 0; ii < 1024; ++ii) {
                float4 c = cbx[ii];
                float ca = (c.z - c.x) * (c.w - c.y);
                bool sup = false;
                if (tid < kept)      sup  = iou_gt(kb0, ka0, c, ca);
                if (tid + 32 < kept) sup |= iou_gt(kb1, ka1, c, ca);
                unsigned m = __ballot_sync(0xffffffffu, sup);
                if (m == 0) {
                    int slot = kept;
                    if (slot < 32) { if (tid == slot)      { kb0 = c; ka0 = ca; } }
                    else           { if (tid == slot - 32) { kb1 = c; ka1 = ca; } }
                    if (tid == 0) s_sel[slot] = cord[ii];
                    kept++;
                    if (kept == 64) break;
                } else if (supp < 64) {
                    if (tid == 0) s_supp[supp] = cord[ii];
                    supp++;
                }
            }
            if (tid == 0) { st[0] = kept; st[1] = supp; }
        }
        __syncthreads();
        if (st[0] >= 64) break;
    }

    // ---- final selection + labels/scores output ----
    __syncthreads();
    const int keptF = st[0];
    if (tid < 64) {
        int oi = (tid < keptF) ? s_sel[tid] : s_supp[tid - keptF];
        g_sel[tid] = oi;
        if (9600 + tid < out_size) d_out[9600 + tid] = (float)labels[oi];
        if (9664 + tid < out_size) d_out[9664 + tid] = scores[oi];
    }
    __syncthreads();

    // ---- pos features: center_size -> bn -> @pos_w + pos_b -> relu ----
    for (int t = tid; t < 64 * 128; t += 1024) {
        int r = t >> 7, c = t & 127;
        int oi = g_sel[r];
        float x1 = boxes[oi * 4 + 0], y1 = boxes[oi * 4 + 1];
        float x2 = boxes[oi * 4 + 2], y2 = boxes[oi * 4 + 3];
        float w = x2 - x1 + 1.f, h = y2 - y1 + 1.f;
        float cs[4] = { x1 + 0.5f * w, y1 + 0.5f * h, w, h };
        float acc = pos_b[c];
        #pragma unroll
        for (int i = 0; i < 4; ++i) {
            float v = (cs[i] - bn_pos[8 + i]) * rsqrtf(bn_pos[12 + i] + 1e-5f)
                      * bn_pos[i] + bn_pos[4 + i];
            acc += v * pos_w[i * 128 + c];
        }
        g_pos[t] = fmaxf(acc, 0.f);
    }
    // ---- embed gather ----
    for (int t = tid; t < 64 * 200; t += 1024) {
        int r = t / 200, c = t - r * 200;
        int lab = labels[g_sel[r]] - 1;
        g_emb[t] = embed_w[lab * 200 + c];
    }
}

// ============================================================
// Kernel 2: split-K GEMM with fused last-block epilogue.
// Block = 64 rows x 64 cols x one K-slice; 256 threads, 4x4 thread tile.
// ASEL 0: virtual A = [features(g_sel) | g_emb | g_pos]  (layer 1)
// ASEL 1: A = g_h1   ASEL 2: A = g_h2
// outsel 1 -> g_h1, 2 -> g_h2, 3 -> dest (d_out, ldo=N)
// ============================================================
template<int ASEL, int FULLN>
__global__ void __launch_bounds__(256) gemm_fused_kernel(
    const float* __restrict__ Wm, const float* __restrict__ bias,
    const float* __restrict__ bn, float* __restrict__ dest,
    int N, int K, int kps, int S, int CB, int outsel, int bnrelu,
    const float* __restrict__ features)
{
    __shared__ float As[32][65];
    __shared__ int ssel[64];
    __shared__ int s_last;

    const int tid = threadIdx.x;
    const int cb = blockIdx.x, sl = blockIdx.y;
    const int col0 = cb * 64 + (tid & 15) * 4;
    const int row0 = (tid >> 4) * 4;
    const int k0 = sl * kps;
    const int k1 = min(k0 + kps, K);

    if (ASEL == 0 && tid < 64) ssel[tid] = g_sel[tid];
    const float* __restrict__ A = (ASEL == 1) ? g_h1 : g_h2;

    float acc[4][4];
    #pragma unroll
    for (int r = 0; r < 4; ++r)
        #pragma unroll
        for (int q = 0; q < 4; ++q) acc[r][q] = 0.f;

    for (int kb = k0; kb < k1; kb += 32) {
        const int kbn = min(32, k1 - kb);
        __syncthreads();
        #pragma unroll
        for (int idx = tid; idx < 64 * 32; idx += 256) {
            int kk = idx & 31, r = idx >> 5;
            float v = 0.f;
            if (kk < kbn) {
                int j = kb + kk;
                if (ASEL == 0) {
                    if (j < 2048)       v = features[(size_t)ssel[r] * 2048 + j];
                    else if (j < 2248)  v = g_emb[r * 200 + (j - 2048)];
                    else                v = g_pos[r * 128 + (j - 2248)];
                } else {
                    v = A[r * H + j];
                }
            }
            As[kk][r] = v;
        }
        __syncthreads();

        #pragma unroll 4
        for (int kk = 0; kk < kbn; ++kk) {
            float w0, w1, w2, w3;
            if (FULLN) {
                const float4 wv = *reinterpret_cast<const float4*>(
                    &Wm[(size_t)(kb + kk) * N + col0]);
                w0 = wv.x; w1 = wv.y; w2 = wv.z; w3 = wv.w;
            } else {
                const float* wp = &Wm[(size_t)(kb + kk) * N];
                w0 = (col0 + 0 < N) ? wp[col0 + 0] : 0.f;
                w1 = (col0 + 1 < N) ? wp[col0 + 1] : 0.f;
                w2 = (col0 + 2 < N) ? wp[col0 + 2] : 0.f;
                w3 = (col0 + 3 < N) ? wp[col0 + 3] : 0.f;
            }
            float a0 = As[kk][row0 + 0], a1 = As[kk][row0 + 1];
            float a2 = As[kk][row0 + 2], a3 = As[kk][row0 + 3];
            acc[0][0] += a0 * w0; acc[0][1] += a0 * w1; acc[0][2] += a0 * w2; acc[0][3] += a0 * w3;
            acc[1][0] += a1 * w0; acc[1][1] += a1 * w1; acc[1][2] += a1 * w2; acc[1][3] += a1 * w3;
            acc[2][0] += a2 * w0; acc[2][1] += a2 * w1; acc[2][2] += a2 * w2; acc[2][3] += a2 * w3;
            acc[3][0] += a3 * w0; acc[3][1] += a3 * w1; acc[3][2] += a3 * w2; acc[3][3] += a3 * w3;
        }
    }

    // ---- write this block's 64x64 partial tile ----
    float* p = g_part + (size_t)(sl * CB + cb) * 4096;
    const int cl = (tid & 15) * 4;
    #pragma unroll
    for (int r = 0; r < 4; ++r)
        *reinterpret_cast<float4*>(&p[(row0 + r) * 64 + cl]) =
            make_float4(acc[r][0], acc[r][1], acc[r][2], acc[r][3]);

    // ---- last block per column-tile reduces + epilogue ----
    __syncthreads();
    if (tid == 0) {
        __threadfence();
        int old = atomicAdd(&g_cnt[cb], 1);
        s_last = (old == S - 1) ? 1 : 0;
    }
    __syncthreads();
    if (!s_last) return;
    __threadfence();

    float* out = (outsel == 1) ? g_h1 : ((outsel == 2) ? g_h2 : dest);
    const int ldo = (outsel == 3) ? N : H;
    for (int idx = tid; idx < 4096; idx += 256) {
        int r = idx >> 6, c = idx & 63;
        int col = cb * 64 + c;
        if (FULLN || col < N) {
            float s = 0.f;
            for (int si = 0; si < S; ++si)
                s += g_part[(size_t)(si * CB + cb) * 4096 + idx];
            s += bias[col];
            if (bnrelu) {
                s = (s - bn[2 * N + col]) * rsqrtf(bn[3 * N + col] + 1e-5f)
                    * bn[col] + bn[N + col];
                s = fmaxf(s, 0.f);
            }
            out[r * ldo + col] = s;
        }
    }
    if (tid == 0) g_cnt[cb] = 0;
}

// ============================================================
extern "C" void kernel_launch(void* const* d_in, const int* in_sizes, int n_in,
                              void* d_out_v, int out_size)
{
    const float* boxes    = (const float*)d_in[0];
    const float* scores   = (const float*)d_in[1];
    const int*   labels   = (const int*)  d_in[2];
    const float* features = (const float*)d_in[3];
    const float* embed_w  = (const float*)d_in[4];
    const float* bn_pos   = (const float*)d_in[5];
    const float* pos_w    = (const float*)d_in[6];
    const float* pos_b    = (const float*)d_in[7];
    const float* lin1_w   = (const float*)d_in[8];
    const float* lin1_b   = (const float*)d_in[9];
    const float* bn1      = (const float*)d_in[10];
    const float* lin2_w   = (const float*)d_in[11];
    const float* lin2_b   = (const float*)d_in[12];
    const float* bn2      = (const float*)d_in[13];
    const float* lin3_w   = (const float*)d_in[14];
    const float* lin3_b   = (const float*)d_in[15];
    const float* bn3      = (const float*)d_in[16];
    const float* lin4_w   = (const float*)d_in[17];
    const float* lin4_b   = (const float*)d_in[18];
    float* d_out = (float*)d_out_v;

    cudaFuncSetAttribute(sortnms_kernel,
                         cudaFuncAttributeMaxDynamicSharedMemorySize, SORT_SMEM);

    // sort + NMS + select + labels/scores out + pos/embed prep
    sortnms_kernel<<<1, 1024, SORT_SMEM>>>(scores, boxes, labels, embed_w,
                                           bn_pos, pos_w, pos_b, d_out, out_size);

    // layer 1: [64,2376]@[2376,1024]  CB=16, S=12 (kps=198)
    gemm_fused_kernel<0, 1><<<dim3(16, 12), 256>>>(
        lin1_w, lin1_b, bn1, d_out, H, D_IN, 198, 12, 16, 1, 1, features);

    // layer 2: [64,1024]@[1024,1024]  CB=16, S=16 (kps=64)
    gemm_fused_kernel<1, 1><<<dim3(16, 16), 256>>>(
        lin2_w, lin2_b, bn2, d_out, H, H, 64, 16, 16, 2, 1, features);

    // layer 3: reads g_h2, writes g_h1
    gemm_fused_kernel<2, 1><<<dim3(16, 16), 256>>>(
        lin3_w, lin3_b, bn3, d_out, H, H, 64, 16, 16, 1, 1, features);

    // layer 4: [64,1024]@[1024,150]  CB=3, S=32 (kps=32), no BN/ReLU, to d_out
    gemm_fused_kernel<1, 0><<<dim3(3, 32), 256>>>(
        lin4_w, lin4_b, bn1, d_out, NCLS, H, 32, 32, 3, 3, 0, features);
}

// round 3
// speedup vs baseline: 1.1870x; 1.1870x over previous
#include <cuda_runtime.h>
#include <cstdint>

#define NBOX 8192
#define M 64
#define D_IN 2376
#define H 1024
#define NCLS 150
#define IOU_T 0.01f

typedef unsigned int u32;
typedef unsigned short u16;
typedef unsigned char u8;

// -------- persistent device scratch (allocation-free rule) --------
__device__ int   g_sel[M];
__device__ float g_emb[M * 200];
__device__ float g_pos[M * 128];
__device__ float g_h1[M * H];
__device__ float g_h2[M * H];
__device__ float g_part[1048576];     // split-K partials: [slice*CB+cb][64*64]
__device__ int   g_cnt[16];           // arrival counters per column tile

// ============================================================
// smem layout for sortnms kernel (bytes)
// ============================================================
#define RS_KEYA 0
#define RS_KEYB 32768
#define RS_IDXA 65536
#define RS_IDXB 81920
#define RS_GH   98304
#define RS_RNK  114688
#define RS_TOT  122880
#define RS_BASE 122944
#define RS_SEL  123008
#define RS_SUPP 123264
#define RS_ST   123520
#define RS_CB   32768
#define RS_CORD 81920
#define SORT_SMEM 123584

__device__ __forceinline__ bool iou_gt(float4 k, float ka, float4 c, float ca) {
    float ix1 = fmaxf(k.x, c.x), iy1 = fmaxf(k.y, c.y);
    float ix2 = fminf(k.z, c.z), iy2 = fminf(k.w, c.w);
    float iw = fmaxf(ix2 - ix1, 0.f), ih = fmaxf(iy2 - iy1, 0.f);
    float inter = iw * ih;
    return inter > IOU_T * (ka + ca - inter + 1e-9f);
}

// ============================================================
// Kernel 1: radix sort + greedy NMS + select + pos/embed prep
// ============================================================
__global__ void __launch_bounds__(1024) sortnms_kernel(
    const float* __restrict__ scores, const float* __restrict__ boxes,
    const int* __restrict__ labels, const float* __restrict__ embed_w,
    const float* __restrict__ bn_pos, const float* __restrict__ pos_w,
    const float* __restrict__ pos_b,
    float* __restrict__ d_out, int out_size)
{
    extern __shared__ unsigned char sm[];
    u32* keyA = (u32*)(sm + RS_KEYA);
    u32* keyB = (u32*)(sm + RS_KEYB);
    u16* idxA = (u16*)(sm + RS_IDXA);
    u16* idxB = (u16*)(sm + RS_IDXB);
    u32* gh   = (u32*)(sm + RS_GH);
    u8*  rnk  = (u8*) (sm + RS_RNK);
    u32* tot  = (u32*)(sm + RS_TOT);
    u32* base = (u32*)(sm + RS_BASE);
    int* s_sel  = (int*)(sm + RS_SEL);
    int* s_supp = (int*)(sm + RS_SUPP);
    int* st     = (int*)(sm + RS_ST);
    float4* cbx = (float4*)(sm + RS_CB);
    int*    cord = (int*)(sm + RS_CORD);

    const int tid = threadIdx.x;
    const int lane = tid & 31;
    const int wrp = tid >> 5;
    const float4* boxes4 = (const float4*)boxes;

    for (int t = tid; t < NBOX; t += 1024) {
        u32 b = __float_as_uint(scores[t]);
        u32 f = b ^ ((b >> 31) ? 0xFFFFFFFFu : 0x80000000u);
        keyA[t] = ~f;
        idxA[t] = (u16)t;
    }
    __syncthreads();

    u32 *src = keyA, *dst = keyB;
    u16 *isrc = idxA, *idst = idxB;
    for (int p = 0; p < 8; ++p) {
        const int sh = p * 4;
        for (int t = tid; t < 4096; t += 1024) gh[t] = 0;
        __syncthreads();
        #pragma unroll
        for (int it = 0; it < 8; ++it) {
            int g = it * 32 + wrp;
            int e = g * 32 + lane;
            u32 k = src[e];
            int d = (k >> sh) & 15;
            unsigned m = __match_any_sync(0xffffffffu, d);
            unsigned lt = m & ((1u << lane) - 1u);
            rnk[e] = (u8)__popc(lt);
            if (lt == 0) gh[g * 16 + d] = __popc(m);
        }
        __syncthreads();
        if (wrp < 16) {
            const int d = wrp;
            u32 carry = 0;
            #pragma unroll
            for (int it = 0; it < 8; ++it) {
                int g = it * 32 + lane;
                u32 v = gh[g * 16 + d];
                u32 x = v;
                #pragma unroll
                for (int o = 1; o < 32; o <<= 1) {
                    u32 y = __shfl_up_sync(0xffffffffu, x, o);
                    if (lane >= o) x += y;
                }
                gh[g * 16 + d] = x - v + carry;
                carry += __shfl_sync(0xffffffffu, x, 31);
            }
            if (lane == 0) tot[d] = carry;
        }
        __syncthreads();
        if (wrp == 0 && lane < 16) {
            u32 v = tot[lane];
            u32 x = v;
            #pragma unroll
            for (int o = 1; o < 16; o <<= 1) {
                u32 y = __shfl_up_sync(0xffffu, x, o);
                if (lane >= o) x += y;
            }
            base[lane] = x - v;
        }
        __syncthreads();
        #pragma unroll
        for (int it = 0; it < 8; ++it) {
            int g = it * 32 + wrp;
            int e = g * 32 + lane;
            u32 k = src[e];
            int d = (k >> sh) & 15;
            u32 pos = base[d] + gh[g * 16 + d] + rnk[e];
            dst[pos] = k;
            idst[pos] = isrc[e];
        }
        __syncthreads();
        u32* tk = src; src = dst; dst = tk;
        u16* ti = isrc; isrc = idst; idst = ti;
    }

    // ---- greedy NMS ----
    float4 kb0 = make_float4(0, 0, 0, 0), kb1 = make_float4(0, 0, 0, 0);
    float ka0 = 0.f, ka1 = 0.f;
    int kept = 0, supp = 0;
    if (tid == 0) { st[0] = 0; st[1] = 0; }

    for (int c0 = 0; c0 < NBOX; c0 += 1024) {
        __syncthreads();
        {
            int oi = (int)isrc[c0 + tid];
            cord[tid] = oi;
            cbx[tid] = boxes4[oi];
        }
        __syncthreads();

        if (tid < 32) {
            #pragma unroll 1
            for (int ii = 0; ii < 1024; ++ii) {
                float4 c = cbx[ii];
                float ca = (c.z - c.x) * (c.w - c.y);
                bool sup = false;
                if (tid < kept)      sup  = iou_gt(kb0, ka0, c, ca);
                if (tid + 32 < kept) sup |= iou_gt(kb1, ka1, c, ca);
                unsigned m = __ballot_sync(0xffffffffu, sup);
                if (m == 0) {
                    int slot = kept;
                    if (slot < 32) { if (tid == slot)      { kb0 = c; ka0 = ca; } }
                    else           { if (tid == slot - 32) { kb1 = c; ka1 = ca; } }
                    if (tid == 0) s_sel[slot] = cord[ii];
                    kept++;
                    if (kept == 64) break;
                } else if (supp < 64) {
                    if (tid == 0) s_supp[supp] = cord[ii];
                    supp++;
                }
            }
            if (tid == 0) { st[0] = kept; st[1] = supp; }
        }
        __syncthreads();
        if (st[0] >= 64) break;
    }

    __syncthreads();
    const int keptF = st[0];
    if (tid < 64) {
        int oi = (tid < keptF) ? s_sel[tid] : s_supp[tid - keptF];
        g_sel[tid] = oi;
        if (9600 + tid < out_size) d_out[9600 + tid] = (float)labels[oi];
        if (9664 + tid < out_size) d_out[9664 + tid] = scores[oi];
    }
    __syncthreads();

    for (int t = tid; t < 64 * 128; t += 1024) {
        int r = t >> 7, c = t & 127;
        int oi = g_sel[r];
        float x1 = boxes[oi * 4 + 0], y1 = boxes[oi * 4 + 1];
        float x2 = boxes[oi * 4 + 2], y2 = boxes[oi * 4 + 3];
        float w = x2 - x1 + 1.f, h = y2 - y1 + 1.f;
        float cs[4] = { x1 + 0.5f * w, y1 + 0.5f * h, w, h };
        float acc = pos_b[c];
        #pragma unroll
        for (int i = 0; i < 4; ++i) {
            float v = (cs[i] - bn_pos[8 + i]) * rsqrtf(bn_pos[12 + i] + 1e-5f)
                      * bn_pos[i] + bn_pos[4 + i];
            acc += v * pos_w[i * 128 + c];
        }
        g_pos[t] = fmaxf(acc, 0.f);
    }
    for (int t = tid; t < 64 * 200; t += 1024) {
        int r = t / 200, c = t - r * 200;
        int lab = labels[g_sel[r]] - 1;
        g_emb[t] = embed_w[lab * 200 + c];
    }
}

// ============================================================
// cp.async helpers
// ============================================================
__device__ __forceinline__ unsigned smem_u32p(const void* p) {
    return (unsigned)__cvta_generic_to_shared(p);
}
__device__ __forceinline__ void cp16(unsigned dst, const float* src) {
    asm volatile("cp.async.cg.shared.global [%0], [%1], 16;" :: "r"(dst), "l"(src));
}
#define CP_COMMIT() asm volatile("cp.async.commit_group;" ::: "memory")
#define CP_WAIT1()  asm volatile("cp.async.wait_group 1;" ::: "memory")

// ============================================================
// Kernel 2: pipelined split-K GEMM with fused last-block epilogue.
// Block = 64 rows x 64 cols x one K-slice; 256 threads, 4x4 thread tile.
// A chunks (64x32) double-buffered via cp.async; W register-prefetched.
// All K-slice lengths must be multiples of 8.
// ============================================================
template<int ASEL, int FULLN, int S>
__global__ void __launch_bounds__(256) gemm2_kernel(
    const float* __restrict__ Wm, const float* __restrict__ bias,
    const float* __restrict__ bn, float* __restrict__ dest,
    int N, int K, int kps, int CB, int outsel, int bnrelu,
    const float* __restrict__ features)
{
    __shared__ float As[2][64][36];
    __shared__ int ssel[64];
    __shared__ int s_last;

    const int tid = threadIdx.x;
    const int cb = blockIdx.x, sl = blockIdx.y;
    const int col0 = cb * 64 + (tid & 15) * 4;
    const int row0 = (tid >> 4) * 4;
    const int k0 = sl * kps;
    const int k1 = min(k0 + kps, K);

    if (ASEL == 0) {
        if (tid < 64) ssel[tid] = g_sel[tid];
        __syncthreads();
    }

    float acc[4][4];
    #pragma unroll
    for (int r = 0; r < 4; ++r)
        #pragma unroll
        for (int q = 0; q < 4; ++q) acc[r][q] = 0.f;

    // ---- stage one 64x32 A chunk into As[buf] via cp.async ----
    auto stage = [&](int buf, int kb) {
        #pragma unroll
        for (int i = 0; i < 2; ++i) {
            int idx = tid + 256 * i;
            int kk4 = (idx & 7) * 4;
            int r = idx >> 3;
            int j = kb + kk4;
            if (j < k1) {
                const float* src;
                if (ASEL == 0) {
                    if (j < 2048)      src = features + (size_t)ssel[r] * 2048 + j;
                    else if (j < 2248) src = g_emb + r * 200 + (j - 2048);
                    else               src = g_pos + r * 128 + (j - 2248);
                } else {
                    const float* A = (ASEL == 1) ? g_h1 : g_h2;
                    src = A + r * H + j;
                }
                cp16(smem_u32p(&As[buf][r][kk4]), src);
            }
        }
    };

    const int nChunk = (k1 - k0 + 31) >> 5;
    stage(0, k0);
    CP_COMMIT();

    for (int c = 0; c < nChunk; ++c) {
        const int kb = k0 + c * 32;
        const int kbn = min(32, k1 - kb);            // multiple of 8
        if (c + 1 < nChunk) stage((c + 1) & 1, kb + 32);
        CP_COMMIT();
        CP_WAIT1();
        __syncthreads();

        const float (*Ab)[36] = As[c & 1];
        const float* wrow = Wm + (size_t)kb * N;
        const int nG = kbn >> 2;                      // groups of 4 kk, nG even

        float4 wcur[4], wnext[4];
        #pragma unroll
        for (int q = 0; q < 4; ++q) {
            if (FULLN) {
                wcur[q] = *reinterpret_cast<const float4*>(wrow + (size_t)q * N + col0);
            } else {
                const float* wp = wrow + (size_t)q * N;
                wcur[q].x = (col0 + 0 < N) ? wp[col0 + 0] : 0.f;
                wcur[q].y = (col0 + 1 < N) ? wp[col0 + 1] : 0.f;
                wcur[q].z = (col0 + 2 < N) ? wp[col0 + 2] : 0.f;
                wcur[q].w = (col0 + 3 < N) ? wp[col0 + 3] : 0.f;
            }
        }

        for (int g = 0; g < nG; ++g) {
            if (g + 1 < nG) {
                #pragma unroll
                for (int q = 0; q < 4; ++q) {
                    const float* wp = wrow + (size_t)((g + 1) * 4 + q) * N;
                    if (FULLN) {
                        wnext[q] = *reinterpret_cast<const float4*>(wp + col0);
                    } else {
                        wnext[q].x = (col0 + 0 < N) ? wp[col0 + 0] : 0.f;
                        wnext[q].y = (col0 + 1 < N) ? wp[col0 + 1] : 0.f;
                        wnext[q].z = (col0 + 2 < N) ? wp[col0 + 2] : 0.f;
                        wnext[q].w = (col0 + 3 < N) ? wp[col0 + 3] : 0.f;
                    }
                }
            }
            #pragma unroll
            for (int q = 0; q < 4; ++q) {
                const int kk = g * 4 + q;
                float a0 = Ab[row0 + 0][kk];
                float a1 = Ab[row0 + 1][kk];
                float a2 = Ab[row0 + 2][kk];
                float a3 = Ab[row0 + 3][kk];
                float w0 = wcur[q].x, w1 = wcur[q].y, w2 = wcur[q].z, w3 = wcur[q].w;
                acc[0][0] += a0 * w0; acc[0][1] += a0 * w1; acc[0][2] += a0 * w2; acc[0][3] += a0 * w3;
                acc[1][0] += a1 * w0; acc[1][1] += a1 * w1; acc[1][2] += a1 * w2; acc[1][3] += a1 * w3;
                acc[2][0] += a2 * w0; acc[2][1] += a2 * w1; acc[2][2] += a2 * w2; acc[2][3] += a2 * w3;
                acc[3][0] += a3 * w0; acc[3][1] += a3 * w1; acc[3][2] += a3 * w2; acc[3][3] += a3 * w3;
            }
            #pragma unroll
            for (int q = 0; q < 4; ++q) wcur[q] = wnext[q];
        }
        __syncthreads();
    }

    // ---- write 64x64 partial tile ----
    float* p = g_part + (size_t)(sl * CB + cb) * 4096;
    const int cl = (tid & 15) * 4;
    #pragma unroll
    for (int r = 0; r < 4; ++r)
        *reinterpret_cast<float4*>(&p[(row0 + r) * 64 + cl]) =
            make_float4(acc[r][0], acc[r][1], acc[r][2], acc[r][3]);

    // ---- last block per column-tile reduces + epilogue ----
    __syncthreads();
    if (tid == 0) {
        __threadfence();
        int old = atomicAdd(&g_cnt[cb], 1);
        s_last = (old == S - 1) ? 1 : 0;
    }
    __syncthreads();
    if (!s_last) return;
    __threadfence();

    float* out = (outsel == 1) ? g_h1 : ((outsel == 2) ? g_h2 : dest);
    const int ldo = (outsel == 3) ? N : H;
    for (int idx = tid; idx < 4096; idx += 256) {
        int r = idx >> 6, cc = idx & 63;
        int col = cb * 64 + cc;
        if (FULLN || col < N) {
            float s = 0.f;
            #pragma unroll
            for (int si = 0; si < S; ++si)
                s += g_part[(size_t)(si * CB + cb) * 4096 + idx];
            s += bias[col];
            if (bnrelu) {
                s = (s - bn[2 * N + col]) * rsqrtf(bn[3 * N + col] + 1e-5f)
                    * bn[col] + bn[N + col];
                s = fmaxf(s, 0.f);
            }
            out[r * ldo + col] = s;
        }
    }
    if (tid == 0) g_cnt[cb] = 0;
}

// ============================================================
extern "C" void kernel_launch(void* const* d_in, const int* in_sizes, int n_in,
                              void* d_out_v, int out_size)
{
    const float* boxes    = (const float*)d_in[0];
    const float* scores   = (const float*)d_in[1];
    const int*   labels   = (const int*)  d_in[2];
    const float* features = (const float*)d_in[3];
    const float* embed_w  = (const float*)d_in[4];
    const float* bn_pos   = (const float*)d_in[5];
    const float* pos_w    = (const float*)d_in[6];
    const float* pos_b    = (const float*)d_in[7];
    const float* lin1_w   = (const float*)d_in[8];
    const float* lin1_b   = (const float*)d_in[9];
    const float* bn1      = (const float*)d_in[10];
    const float* lin2_w   = (const float*)d_in[11];
    const float* lin2_b   = (const float*)d_in[12];
    const float* bn2      = (const float*)d_in[13];
    const float* lin3_w   = (const float*)d_in[14];
    const float* lin3_b   = (const float*)d_in[15];
    const float* bn3      = (const float*)d_in[16];
    const float* lin4_w   = (const float*)d_in[17];
    const float* lin4_b   = (const float*)d_in[18];
    float* d_out = (float*)d_out_v;

    cudaFuncSetAttribute(sortnms_kernel,
                         cudaFuncAttributeMaxDynamicSharedMemorySize, SORT_SMEM);

    sortnms_kernel<<<1, 1024, SORT_SMEM>>>(scores, boxes, labels, embed_w,
                                           bn_pos, pos_w, pos_b, d_out, out_size);

    // L1: [64,2376]@[2376,1024]  CB=16, S=8, kps=304 (slices 7x304 + 248, all mult 8)
    gemm2_kernel<0, 1, 8><<<dim3(16, 8), 256>>>(
        lin1_w, lin1_b, bn1, d_out, H, D_IN, 304, 16, 1, 1, features);

    // L2: [64,1024]@[1024,1024]  CB=16, S=8, kps=128
    gemm2_kernel<1, 1, 8><<<dim3(16, 8), 256>>>(
        lin2_w, lin2_b, bn2, d_out, H, H, 128, 16, 2, 1, features);

    // L3: reads g_h2, writes g_h1
    gemm2_kernel<2, 1, 8><<<dim3(16, 8), 256>>>(
        lin3_w, lin3_b, bn3, d_out, H, H, 128, 16, 1, 1, features);

    // L4: [64,1024]@[1024,150]  CB=3, S=16, kps=64, no BN/ReLU, to d_out
    gemm2_kernel<1, 0, 16><<<dim3(3, 16), 256>>>(
        lin4_w, lin4_b, bn1, d_out, NCLS, H, 64, 3, 3, 0, features);
}

// round 5
// speedup vs baseline: 1.2524x; 1.0551x over previous
#include <cuda_runtime.h>
#include <cstdint>

#define NBOX 8192
#define M 64
#define D_IN 2376
#define H 1024
#define NCLS 150
#define IOU_T 0.01f

typedef unsigned int u32;
typedef unsigned short u16;
typedef unsigned char u8;

// -------- persistent device scratch (allocation-free rule) --------
__device__ int   g_sel[M];
__device__ float g_emb[M * 200];
__device__ float g_pos[M * 128];
__device__ float g_h1[M * H];
__device__ float g_h2[M * H];
__device__ float g_part[1048576];     // split-K partials: [slice*CB+cb][64*64]
__device__ int   g_cnt[16];           // arrival counters per column tile

// ============================================================
// smem layout for sortnms kernel (bytes)
// ============================================================
#define RS_KEYA 0
#define RS_KEYB 32768
#define RS_IDXA 65536
#define RS_IDXB 81920
#define RS_GH   98304
#define RS_RNK  114688
#define RS_TOT  122880
#define RS_BASE 122944
#define RS_SEL  123008
#define RS_SUPP 123264
#define RS_ST   123520
#define RS_CB   32768
#define RS_CORD 81920
#define SORT_SMEM 123584

__device__ __forceinline__ bool iou_gt(float4 k, float ka, float4 c, float ca) {
    float ix1 = fmaxf(k.x, c.x), iy1 = fmaxf(k.y, c.y);
    float ix2 = fminf(k.z, c.z), iy2 = fminf(k.w, c.w);
    float iw = fmaxf(ix2 - ix1, 0.f), ih = fmaxf(iy2 - iy1, 0.f);
    float inter = iw * ih;
    return inter > IOU_T * (ka + ca - inter + 1e-9f);
}

// ============================================================
// Kernel 1: radix sort + greedy NMS + select + pos/embed prep
// ============================================================
__global__ void __launch_bounds__(1024) sortnms_kernel(
    const float* __restrict__ scores, const float* __restrict__ boxes,
    const int* __restrict__ labels, const float* __restrict__ embed_w,
    const float* __restrict__ bn_pos, const float* __restrict__ pos_w,
    const float* __restrict__ pos_b,
    float* __restrict__ d_out, int out_size)
{
    extern __shared__ unsigned char sm[];
    u32* keyA = (u32*)(sm + RS_KEYA);
    u32* keyB = (u32*)(sm + RS_KEYB);
    u16* idxA = (u16*)(sm + RS_IDXA);
    u16* idxB = (u16*)(sm + RS_IDXB);
    u32* gh   = (u32*)(sm + RS_GH);
    u8*  rnk  = (u8*) (sm + RS_RNK);
    u32* tot  = (u32*)(sm + RS_TOT);
    u32* base = (u32*)(sm + RS_BASE);
    int* s_sel  = (int*)(sm + RS_SEL);
    int* s_supp = (int*)(sm + RS_SUPP);
    int* st     = (int*)(sm + RS_ST);
    float4* cbx = (float4*)(sm + RS_CB);
    int*    cord = (int*)(sm + RS_CORD);

    const int tid = threadIdx.x;
    const int lane = tid & 31;
    const int wrp = tid >> 5;
    const float4* boxes4 = (const float4*)boxes;

    for (int t = tid; t < NBOX; t += 1024) {
        u32 b = __float_as_uint(scores[t]);
        u32 f = b ^ ((b >> 31) ? 0xFFFFFFFFu : 0x80000000u);
        keyA[t] = ~f;
        idxA[t] = (u16)t;
    }
    __syncthreads();

    u32 *src = keyA, *dst = keyB;
    u16 *isrc = idxA, *idst = idxB;
    for (int p = 0; p < 8; ++p) {
        const int sh = p * 4;
        for (int t = tid; t < 4096; t += 1024) gh[t] = 0;
        __syncthreads();
        #pragma unroll
        for (int it = 0; it < 8; ++it) {
            int g = it * 32 + wrp;
            int e = g * 32 + lane;
            u32 k = src[e];
            int d = (k >> sh) & 15;
            unsigned m = __match_any_sync(0xffffffffu, d);
            unsigned lt = m & ((1u << lane) - 1u);
            rnk[e] = (u8)__popc(lt);
            if (lt == 0) gh[g * 16 + d] = __popc(m);
        }
        __syncthreads();
        if (wrp < 16) {
            const int d = wrp;
            u32 carry = 0;
            #pragma unroll
            for (int it = 0; it < 8; ++it) {
                int g = it * 32 + lane;
                u32 v = gh[g * 16 + d];
                u32 x = v;
                #pragma unroll
                for (int o = 1; o < 32; o <<= 1) {
                    u32 y = __shfl_up_sync(0xffffffffu, x, o);
                    if (lane >= o) x += y;
                }
                gh[g * 16 + d] = x - v + carry;
                carry += __shfl_sync(0xffffffffu, x, 31);
            }
            if (lane == 0) tot[d] = carry;
        }
        __syncthreads();
        if (wrp == 0 && lane < 16) {
            u32 v = tot[lane];
            u32 x = v;
            #pragma unroll
            for (int o = 1; o < 16; o <<= 1) {
                u32 y = __shfl_up_sync(0xffffu, x, o);
                if (lane >= o) x += y;
            }
            base[lane] = x - v;
        }
        __syncthreads();
        #pragma unroll
        for (int it = 0; it < 8; ++it) {
            int g = it * 32 + wrp;
            int e = g * 32 + lane;
            u32 k = src[e];
            int d = (k >> sh) & 15;
            u32 pos = base[d] + gh[g * 16 + d] + rnk[e];
            dst[pos] = k;
            idst[pos] = isrc[e];
        }
        __syncthreads();
        u32* tk = src; src = dst; dst = tk;
        u16* ti = isrc; isrc = idst; idst = ti;
    }

    // ---- greedy NMS ----
    float4 kb0 = make_float4(0, 0, 0, 0), kb1 = make_float4(0, 0, 0, 0);
    float ka0 = 0.f, ka1 = 0.f;
    int kept = 0, supp = 0;
    if (tid == 0) { st[0] = 0; st[1] = 0; }

    for (int c0 = 0; c0 < NBOX; c0 += 1024) {
        __syncthreads();
        {
            int oi = (int)isrc[c0 + tid];
            cord[tid] = oi;
            cbx[tid] = boxes4[oi];
        }
        __syncthreads();

        if (tid < 32) {
            #pragma unroll 1
            for (int ii = 0; ii < 1024; ++ii) {
                float4 c = cbx[ii];
                float ca = (c.z - c.x) * (c.w - c.y);
                bool sup = false;
                if (tid < kept)      sup  = iou_gt(kb0, ka0, c, ca);
                if (tid + 32 < kept) sup |= iou_gt(kb1, ka1, c, ca);
                unsigned m = __ballot_sync(0xffffffffu, sup);
                if (m == 0) {
                    int slot = kept;
                    if (slot < 32) { if (tid == slot)      { kb0 = c; ka0 = ca; } }
                    else           { if (tid == slot - 32) { kb1 = c; ka1 = ca; } }
                    if (tid == 0) s_sel[slot] = cord[ii];
                    kept++;
                    if (kept == 64) break;
                } else if (supp < 64) {
                    if (tid == 0) s_supp[supp] = cord[ii];
                    supp++;
                }
            }
            if (tid == 0) { st[0] = kept; st[1] = supp; }
        }
        __syncthreads();
        if (st[0] >= 64) break;
    }

    __syncthreads();
    const int keptF = st[0];
    if (tid < 64) {
        int oi = (tid < keptF) ? s_sel[tid] : s_supp[tid - keptF];
        g_sel[tid] = oi;
        if (9600 + tid < out_size) d_out[9600 + tid] = (float)labels[oi];
        if (9664 + tid < out_size) d_out[9664 + tid] = scores[oi];
    }
    __syncthreads();

    for (int t = tid; t < 64 * 128; t += 1024) {
        int r = t >> 7, c = t & 127;
        int oi = g_sel[r];
        float x1 = boxes[oi * 4 + 0], y1 = boxes[oi * 4 + 1];
        float x2 = boxes[oi * 4 + 2], y2 = boxes[oi * 4 + 3];
        float w = x2 - x1 + 1.f, h = y2 - y1 + 1.f;
        float cs[4] = { x1 + 0.5f * w, y1 + 0.5f * h, w, h };
        float acc = pos_b[c];
        #pragma unroll
        for (int i = 0; i < 4; ++i) {
            float v = (cs[i] - bn_pos[8 + i]) * rsqrtf(bn_pos[12 + i] + 1e-5f)
                      * bn_pos[i] + bn_pos[4 + i];
            acc += v * pos_w[i * 128 + c];
        }
        g_pos[t] = fmaxf(acc, 0.f);
    }
    for (int t = tid; t < 64 * 200; t += 1024) {
        int r = t / 200, c = t - r * 200;
        int lab = labels[g_sel[r]] - 1;
        g_emb[t] = embed_w[lab * 200 + c];
    }
}

// ============================================================
// cp.async helpers
// ============================================================
__device__ __forceinline__ unsigned smem_u32p(const void* p) {
    return (unsigned)__cvta_generic_to_shared(p);
}
__device__ __forceinline__ void cp16(unsigned dst, const float* src) {
    asm volatile("cp.async.cg.shared.global [%0], [%1], 16;" :: "r"(dst), "l"(src));
}
__device__ __forceinline__ void cp4(unsigned dst, const float* src) {
    asm volatile("cp.async.ca.shared.global [%0], [%1], 4;" :: "r"(dst), "l"(src));
}
#define CP_COMMIT() asm volatile("cp.async.commit_group;" ::: "memory")
#define CP_WAIT2()  asm volatile("cp.async.wait_group 2;" ::: "memory")

// ============================================================
// Kernel 2: deep-pipelined split-K GEMM, fused last-block epilogue.
// Block = 64 rows x 64 cols x one K-slice; 256 threads, 4x4 thread tile.
// Both A (64x16) and W (16x64) chunks flow through a 4-stage cp.async
// pipeline (3 stages in flight -> ~3 compute-stages of latency cover).
// K-slice lengths must be multiples of 8.
// ============================================================
template<int ASEL, int FULLN, int S>
__global__ void __launch_bounds__(256) gemm3_kernel(
    const float* __restrict__ Wm, const float* __restrict__ bias,
    const float* __restrict__ bn, float* __restrict__ dest,
    int N, int K, int kps, int CB, int outsel, int bnrelu,
    const float* __restrict__ features)
{
    __shared__ float As[4][64][20];   // [stage][row][kk]  (pad 20)
    __shared__ float Ws[4][16][68];   // [stage][kk][col]  (pad 68)
    __shared__ int ssel[64];
    __shared__ int s_last;

    const int tid = threadIdx.x;
    const int cb = blockIdx.x, sl = blockIdx.y;
    const int row0 = (tid >> 4) * 4;
    const int cl   = (tid & 15) * 4;
    const int k0 = sl * kps;
    const int k1 = min(k0 + kps, K);

    if (ASEL == 0 && tid < 64) ssel[tid] = g_sel[tid];
    if (!FULLN) {   // pre-zero W buffers (cols >= N stay 0 forever)
        for (int t = tid; t < 4 * 16 * 68; t += 256) ((float*)Ws)[t] = 0.f;
    }
    __syncthreads();

    float acc[4][4];
    #pragma unroll
    for (int r = 0; r < 4; ++r)
        #pragma unroll
        for (int q = 0; q < 4; ++q) acc[r][q] = 0.f;

    // ---- stage one (A,W) chunk pair into buffers [buf] ----
    auto stageA = [&](int buf, int kb) {
        const int r = tid >> 2;          // 0..63
        const int kk4 = (tid & 3) * 4;   // 0,4,8,12
        const int j = kb + kk4;
        if (j < k1) {
            const float* src;
            if (ASEL == 0) {
                if (j < 2048)      src = features + (size_t)ssel[r] * 2048 + j;
                else if (j < 2248) src = g_emb + r * 200 + (j - 2048);
                else               src = g_pos + r * 128 + (j - 2248);
            } else {
                src = ((ASEL == 1) ? g_h1 : g_h2) + r * H + j;
            }
            cp16(smem_u32p(&As[buf][r][kk4]), src);
        }
    };
    auto stageW = [&](int buf, int kb) {
        const int kk = tid >> 4;         // 0..15
        const int n4 = (tid & 15) * 4;
        const int j = kb + kk;
        if (j < k1) {
            if (FULLN) {
                cp16(smem_u32p(&Ws[buf][kk][n4]), Wm + (size_t)j * N + cb * 64 + n4);
            } else {
                #pragma unroll
                for (int q = 0; q < 4; ++q) {
                    int col = cb * 64 + n4 + q;
                    if (col < N)
                        cp4(smem_u32p(&Ws[buf][kk][n4 + q]), Wm + (size_t)j * N + col);
                }
            }
        }
    };

    const int nChunk = (k1 - k0 + 15) >> 4;
    #pragma unroll
    for (int s = 0; s < 3; ++s) {
        if (s < nChunk) { stageA(s, k0 + s * 16); stageW(s, k0 + s * 16); }
        CP_COMMIT();
    }

    for (int c = 0; c < nChunk; ++c) {
        CP_WAIT2();
        __syncthreads();
        {   // issue stage c+3 (into buffer (c-1)&3, whose reads are done)
            const int s = c + 3;
            if (s < nChunk) { stageA(s & 3, k0 + s * 16); stageW(s & 3, k0 + s * 16); }
            CP_COMMIT();
        }
        const int kbn = min(16, k1 - (k0 + c * 16));
        const float (*Ab)[20] = As[c & 3];
        const float (*Wb)[68] = Ws[c & 3];

        #define KK_BODY(kk)                                                        \
        {                                                                          \
            float a0 = Ab[row0 + 0][kk], a1 = Ab[row0 + 1][kk];                    \
            float a2 = Ab[row0 + 2][kk], a3 = Ab[row0 + 3][kk];                    \
            float4 w = *reinterpret_cast<const float4*>(&Wb[kk][cl]);              \
            acc[0][0] += a0 * w.x; acc[0][1] += a0 * w.y;                          \
            acc[0][2] += a0 * w.z; acc[0][3] += a0 * w.w;                          \
            acc[1][0] += a1 * w.x; acc[1][1] += a1 * w.y;                          \
            acc[1][2] += a1 * w.z; acc[1][3] += a1 * w.w;                          \
            acc[2][0] += a2 * w.x; acc[2][1] += a2 * w.y;                          \
            acc[2][2] += a2 * w.z; acc[2][3] += a2 * w.w;                          \
            acc[3][0] += a3 * w.x; acc[3][1] += a3 * w.y;                          \
            acc[3][2] += a3 * w.z; acc[3][3] += a3 * w.w;                          \
        }

        if (kbn == 16) {
            #pragma unroll
            for (int kk = 0; kk < 16; ++kk) KK_BODY(kk)
        } else {
            #pragma unroll 8
            for (int kk = 0; kk < kbn; ++kk) KK_BODY(kk)
        }
        #undef KK_BODY
    }

    // ---- write 64x64 partial tile ----
    float* p = g_part + (size_t)(sl * CB + cb) * 4096;
    #pragma unroll
    for (int r = 0; r < 4; ++r)
        *reinterpret_cast<float4*>(&p[(row0 + r) * 64 + cl]) =
            make_float4(acc[r][0], acc[r][1], acc[r][2], acc[r][3]);

    // ---- last block per column-tile reduces + epilogue ----
    __syncthreads();
    if (tid == 0) {
        __threadfence();
        int old = atomicAdd(&g_cnt[cb], 1);
        s_last = (old == S - 1) ? 1 : 0;
    }
    __syncthreads();
    if (!s_last) return;
    __threadfence();

    float* out = (outsel == 1) ? g_h1 : ((outsel == 2) ? g_h2 : dest);
    const int ldo = (outsel == 3) ? N : H;
    for (int idx = tid; idx < 4096; idx += 256) {
        int r = idx >> 6, cc = idx & 63;
        int col = cb * 64 + cc;
        if (FULLN || col < N) {
            float s = 0.f;
            #pragma unroll
            for (int si = 0; si < S; ++si)
                s += g_part[(size_t)(si * CB + cb) * 4096 + idx];
            s += bias[col];
            if (bnrelu) {
                s = (s - bn[2 * N + col]) * rsqrtf(bn[3 * N + col] + 1e-5f)
                    * bn[col] + bn[N + col];
                s = fmaxf(s, 0.f);
            }
            out[r * ldo + col] = s;
        }
    }
    if (tid == 0) g_cnt[cb] = 0;
}

// ============================================================
extern "C" void kernel_launch(void* const* d_in, const int* in_sizes, int n_in,
                              void* d_out_v, int out_size)
{
    const float* boxes    = (const float*)d_in[0];
    const float* scores   = (const float*)d_in[1];
    const int*   labels   = (const int*)  d_in[2];
    const float* features = (const float*)d_in[3];
    const float* embed_w  = (const float*)d_in[4];
    const float* bn_pos   = (const float*)d_in[5];
    const float* pos_w    = (const float*)d_in[6];
    const float* pos_b    = (const float*)d_in[7];
    const float* lin1_w   = (const float*)d_in[8];
    const float* lin1_b   = (const float*)d_in[9];
    const float* bn1      = (const float*)d_in[10];
    const float* lin2_w   = (const float*)d_in[11];
    const float* lin2_b   = (const float*)d_in[12];
    const float* bn2      = (const float*)d_in[13];
    const float* lin3_w   = (const float*)d_in[14];
    const float* lin3_b   = (const float*)d_in[15];
    const float* bn3      = (const float*)d_in[16];
    const float* lin4_w   = (const float*)d_in[17];
    const float* lin4_b   = (const float*)d_in[18];
    float* d_out = (float*)d_out_v;

    cudaFuncSetAttribute(sortnms_kernel,
                         cudaFuncAttributeMaxDynamicSharedMemorySize, SORT_SMEM);

    sortnms_kernel<<<1, 1024, SORT_SMEM>>>(scores, boxes, labels, embed_w,
                                           bn_pos, pos_w, pos_b, d_out, out_size);

    // L1: [64,2376]@[2376,1024]  CB=16, S=15, kps=160 (14x160 + 136, mult 8)
    gemm3_kernel<0, 1, 15><<<dim3(16, 15), 256>>>(
        lin1_w, lin1_b, bn1, d_out, H, D_IN, 160, 16, 1, 1, features);

    // L2: [64,1024]@[1024,1024]  CB=16, S=16, kps=64
    gemm3_kernel<1, 1, 16><<<dim3(16, 16), 256>>>(
        lin2_w, lin2_b, bn2, d_out, H, H, 64, 16, 2, 1, features);

    // L3: reads g_h2, writes g_h1
    gemm3_kernel<2, 1, 16><<<dim3(16, 16), 256>>>(
        lin3_w, lin3_b, bn3, d_out, H, H, 64, 16, 1, 1, features);

    // L4: [64,1024]@[1024,150]  CB=3, S=16, kps=64, no BN/ReLU, to d_out
    gemm3_kernel<1, 0, 16><<<dim3(3, 16), 256>>>(
        lin4_w, lin4_b, bn1, d_out, NCLS, H, 64, 3, 3, 0, features);
}